// round 13
// baseline (speedup 1.0000x reference)
#include <cuda_runtime.h>
#include <cstdint>
#include <cstddef>

typedef unsigned long long ull;

#define S_LEN 512
#define B_SZ  256
#define D_SZ  128
#define R_SZ  2048

__device__ float  g_hist[(size_t)S_LEN * B_SZ * R_SZ];
__device__ double g_pc_part[8];
__device__ double g_mse_part[128];

__device__ __forceinline__ ull pk2(float lo, float hi) {
    ull r; asm("mov.b64 %0, {%1,%2};" : "=l"(r) : "f"(lo), "f"(hi)); return r;
}
__device__ __forceinline__ void upk2(float& lo, float& hi, ull v) {
    asm("mov.b64 {%0,%1}, %2;" : "=f"(lo), "=f"(hi) : "l"(v));
}
__device__ __forceinline__ ull fma2(ull a, ull b, ull c) {
    ull d; asm("fma.rn.f32x2 %0, %1, %2, %3;" : "=l"(d) : "l"(a), "l"(b), "l"(c)); return d;
}
__device__ __forceinline__ float clip5(float v) { return fminf(fmaxf(v, -5.f), 5.f); }

// XLA:GPU-contracted oscillator step (matched recipe — DO NOT CHANGE)
__device__ __forceinline__ float osc_upd(float f, float& x, float& y,
                                         float a, float g2, float w2) {
    float gy = __fmul_rn(g2, y);
    float ac = fmaf(-w2, x, fmaf(a, f, -gy));
    float xn = clip5(fmaf(0.5f, y, x));
    float yn = clip5(fmaf(0.5f, ac, y));
    x = xn; y = yn;
    return xn;
}

// ============ Phase A: persistent recurrence ============
// Grid (16 col-blocks, 8 row-blocks), 256 threads. Thread tile 4r x 4c.
// smem: wt2[128 d][128 c] as (w,w) ull pairs (128KB) +
//       double-buffered xs[2][128 d][32 rows] floats (2x16KB). Total 160KB.
// Inner loop: 6 LDS.128 + 16 FFMA2, zero pack MOVs.
__global__ void __launch_bounds__(256, 1) phaseA_kernel(
    const float* __restrict__ inputs,
    const float* __restrict__ om_in, const float* __restrict__ ga_in, const float* __restrict__ al_in,
    const float* __restrict__ Wp,    const float* __restrict__ bp,
    const float* __restrict__ om_r,  const float* __restrict__ ga_r,  const float* __restrict__ al_r,
    const float* __restrict__ om_o,  const float* __restrict__ ga_o,  const float* __restrict__ al_o)
{
    const int cb  = blockIdx.x;   // 0..15 reservoir col block
    const int rb  = blockIdx.y;   // 0..7  batch row block
    const int tid = threadIdx.x;

    extern __shared__ char smem_raw[];
    ull*   wt2 = (ull*)smem_raw;                         // [128 d][128 c] (w,w)
    float* xs0 = (float*)(smem_raw + 131072);            // [128 d][32 rows]
    float* xs1 = xs0 + 128 * 32;

    __shared__ float  pa[128], pg[128], pw[128];
    __shared__ double redd[256];

    // stage W_proj tile transposed + duplicated: wt2[d][c] = (Wp[cb*128+c][d]) x2
    // i -> c = i&127 (lane-contiguous stores), dq = i>>7, d0 = dq*4
    for (int i = tid; i < 4096; i += 256) {
        int c = i & 127, d0 = (i >> 7) << 2;
        float4 v = *(const float4*)(Wp + ((size_t)(cb * 128 + c)) * D_SZ + d0);
        wt2[(size_t)(d0+0)*128 + c] = pk2(v.x, v.x);
        wt2[(size_t)(d0+1)*128 + c] = pk2(v.y, v.y);
        wt2[(size_t)(d0+2)*128 + c] = pk2(v.z, v.z);
        wt2[(size_t)(d0+3)*128 + c] = pk2(v.w, v.w);
    }
    if (tid < 128) {
        pa[tid] = al_in[tid];
        pg[tid] = __fmul_rn(2.f, fabsf(ga_in[tid]));
        float o = fabsf(om_in[tid]); pw[tid] = __fmul_rn(o, o);
    }

    // input-oscillator mapping: row = lane, 16 consecutive d per warp
    const int irow = tid & 31;            // 0..31
    const int dch  = (tid >> 5) << 4;     // warp*16
    const int gb_i = rb * 32 + irow;

    // GEMM mapping: 4 rows x 4 cols per thread (row-pair f32x2 packing)
    const int lane = tid & 31, warp = tid >> 5;
    const int r0 = (lane & 7) << 2;
    const int c0 = warp * 16 + ((lane >> 3) << 2);

    float par[4], pgr[4], pwr[4], pao[4], pgo[4], pwo[4], bpv[4];
    {
        int rbase = cb * 128 + c0;
        #pragma unroll
        for (int j = 0; j < 4; ++j) {
            par[j] = al_r[rbase+j];
            pgr[j] = __fmul_rn(2.f, fabsf(ga_r[rbase+j]));
            float o = fabsf(om_r[rbase+j]); pwr[j] = __fmul_rn(o, o);
            pao[j] = al_o[rbase+j];
            pgo[j] = __fmul_rn(2.f, fabsf(ga_o[rbase+j]));
            float q = fabsf(om_o[rbase+j]); pwo[j] = __fmul_rn(q, q);
            bpv[j] = bp[rbase+j];
        }
    }

    float x_in[16], y_in[16], xr[16], yr[16], xo[16], yo[16];
    #pragma unroll
    for (int k = 0; k < 16; ++k) { x_in[k]=0.f; y_in[k]=0.f; xr[k]=0.f; yr[k]=0.f; xo[k]=0.f; yo[k]=0.f; }

    double lin = 0.0, lmse = 0.0;

    float inpv[16];
    {
        const float* p = inputs + (size_t)gb_i * (S_LEN * D_SZ) + dch;
        #pragma unroll
        for (int q = 0; q < 4; ++q) {
            float4 v = *(const float4*)(p + q*4);
            inpv[q*4]=v.x; inpv[q*4+1]=v.y; inpv[q*4+2]=v.z; inpv[q*4+3]=v.w;
        }
    }
    __syncthreads();   // staging complete before any use

    for (int t = 0; t < S_LEN; ++t) {
        float* xs = (t & 1) ? xs1 : xs0;

        if (t > 0) {
            float ls = 0.f;
            #pragma unroll
            for (int k = 0; k < 16; ++k) { float df = x_in[k]-inpv[k]; ls = fmaf(df, df, ls); }
            lin += (double)ls;
        }
        #pragma unroll
        for (int k = 0; k < 16; ++k) {
            int d = dch + k;
            osc_upd(inpv[k], x_in[k], y_in[k], pa[d], pg[d], pw[d]);
        }
        #pragma unroll
        for (int k = 0; k < 16; ++k)
            xs[(dch + k) * 32 + irow] = x_in[k];
        __syncthreads();   // the ONLY barrier per step (double-buffered xs)

        {   // prefetch next input slice under the GEMM
            int tn = (t < S_LEN-1) ? t+1 : t;
            const float* p = inputs + (size_t)gb_i * (S_LEN*D_SZ) + (size_t)tn * D_SZ + dch;
            #pragma unroll
            for (int q = 0; q < 4; ++q) {
                float4 v = *(const float4*)(p + q*4);
                inpv[q*4]=v.x; inpv[q*4+1]=v.y; inpv[q*4+2]=v.z; inpv[q*4+3]=v.w;
            }
        }

        // GEMM1 tile: proj = x_in @ Wp^T
        // acc[rp][j] packs rows (r0+2rp, r0+2rp+1) for col c0+j.
        // Per element: acc=0, ascending-d fma chain — identical math.
        ull acc[2][4];
        #pragma unroll
        for (int j = 0; j < 4; ++j) { acc[0][j] = 0ull; acc[1][j] = 0ull; }

        #pragma unroll 8
        for (int d = 0; d < 128; d += 2) {
            float4 xa = *(const float4*)(xs + d*32 + r0);         // rows r0..r0+3 @ d
            float4 xb = *(const float4*)(xs + (d+1)*32 + r0);     // rows r0..r0+3 @ d+1
            ulonglong2 wa0 = *(const ulonglong2*)(wt2 + (size_t)d*128 + c0);       // (c0,c0),(c1,c1)
            ulonglong2 wa1 = *(const ulonglong2*)(wt2 + (size_t)d*128 + c0 + 2);   // (c2,c2),(c3,c3)
            ulonglong2 wb0 = *(const ulonglong2*)(wt2 + (size_t)(d+1)*128 + c0);
            ulonglong2 wb1 = *(const ulonglong2*)(wt2 + (size_t)(d+1)*128 + c0 + 2);
            ull xa0 = pk2(xa.x, xa.y), xa1 = pk2(xa.z, xa.w);   // register-pair aliases (free)
            ull xb0 = pk2(xb.x, xb.y), xb1 = pk2(xb.z, xb.w);
            acc[0][0] = fma2(xa0, wa0.x, acc[0][0]);
            acc[1][0] = fma2(xa1, wa0.x, acc[1][0]);
            acc[0][1] = fma2(xa0, wa0.y, acc[0][1]);
            acc[1][1] = fma2(xa1, wa0.y, acc[1][1]);
            acc[0][2] = fma2(xa0, wa1.x, acc[0][2]);
            acc[1][2] = fma2(xa1, wa1.x, acc[1][2]);
            acc[0][3] = fma2(xa0, wa1.y, acc[0][3]);
            acc[1][3] = fma2(xa1, wa1.y, acc[1][3]);
            acc[0][0] = fma2(xb0, wb0.x, acc[0][0]);
            acc[1][0] = fma2(xb1, wb0.x, acc[1][0]);
            acc[0][1] = fma2(xb0, wb0.y, acc[0][1]);
            acc[1][1] = fma2(xb1, wb0.y, acc[1][1]);
            acc[0][2] = fma2(xb0, wb1.x, acc[0][2]);
            acc[1][2] = fma2(xb1, wb1.x, acc[1][2]);
            acc[0][3] = fma2(xb0, wb1.y, acc[0][3]);
            acc[1][3] = fma2(xb1, wb1.y, acc[1][3]);
        }

        // unpack: element (i row, j col), i = 2*rp + half
        float fv[4][4];
        #pragma unroll
        for (int rp = 0; rp < 2; ++rp)
            #pragma unroll
            for (int j = 0; j < 4; ++j) {
                float lo, hi; upk2(lo, hi, acc[rp][j]);
                fv[2*rp][j] = lo; fv[2*rp+1][j] = hi;
            }

        float ls2 = 0.f;
        #pragma unroll
        for (int i = 0; i < 4; ++i) {
            #pragma unroll
            for (int j = 0; j < 4; ++j) {
                int k = i*4 + j;
                float f = __fadd_rn(fv[i][j], bpv[j]);   // bias after dot (matched)
                float xrn = osc_upd(f,   xr[k], yr[k], par[j], pgr[j], pwr[j]);
                float xon = osc_upd(xrn, xo[k], yo[k], pao[j], pgo[j], pwo[j]);
                float df = xon - xrn;
                ls2 = fmaf(df, df, ls2);
            }
        }
        lmse += (double)ls2;

        size_t hb = ((size_t)t * B_SZ + rb*32 + r0) * R_SZ + cb*128 + c0;
        #pragma unroll
        for (int i = 0; i < 4; ++i)
            *(float4*)(g_hist + hb + (size_t)i * R_SZ) =
                make_float4(xo[i*4], xo[i*4+1], xo[i*4+2], xo[i*4+3]);
    }

    __syncthreads();
    redd[tid] = lin; __syncthreads();
    for (int s = 128; s > 0; s >>= 1) { if (tid < s) redd[tid] += redd[tid+s]; __syncthreads(); }
    if (tid == 0 && cb == 0) g_pc_part[rb] = redd[0];
    __syncthreads();
    redd[tid] = lmse; __syncthreads();
    for (int s = 128; s > 0; s >>= 1) { if (tid < s) redd[tid] += redd[tid+s]; __syncthreads(); }
    if (tid == 0) g_mse_part[rb*16 + cb] = redd[0];
}

// ============ Phase B: preds = hist @ W_read^T + b_read ============
// CTA tile: 128 rows x 64 cols. Grid (1024, 2), 256 threads.
// Thread: 8 rows (4 row-pairs spaced 32) x 4 cols. k-major smem staging.
// W staged pre-duplicated as (w,w) ull pairs — no dup MOVs in inner loop.
#define AS_PITCH 130
#define WS2_PITCH 66
__global__ void __launch_bounds__(256, 2) gemm2_kernel(
    const float* __restrict__ Wr, const float* __restrict__ brd, float* __restrict__ out)
{
    __shared__ __align__(16) ull   ws2[32 * WS2_PITCH];  // ws2[k][c] = (w,w), c<64
    __shared__ __align__(16) float as2[32 * AS_PITCH];   // as2[k][r], r<128

    const int tid = threadIdx.x;
    const int lane = tid & 31, warp = tid >> 5;
    const int rg = lane & 15, cg = lane >> 4;
    const int r0 = rg * 2;                   // rows r0 + rp*32 + {0,1}
    const int c0 = warp * 8 + cg * 4;        // local col base (0..60 within 64)
    const int C0 = blockIdx.y * 64;
    const size_t mBase = (size_t)blockIdx.x * 128;

    ull acc[4][4];
    #pragma unroll
    for (int rp = 0; rp < 4; ++rp)
        #pragma unroll
        for (int j = 0; j < 4; ++j) acc[rp][j] = 0ull;

    for (int kc = 0; kc < R_SZ; kc += 32) {
        __syncthreads();
        // stage W chunk k-major duplicated: ws2[k][c] = (Wr[(C0+c)*R + kc+k]) x2
        // i -> c = i&63 (lane-contiguous stores), kk = (i>>6)*4
        for (int i = tid; i < 512; i += 256) {
            int c = i & 63, kk = (i >> 6) << 2;
            float4 v = *(const float4*)(Wr + (size_t)(C0 + c) * R_SZ + kc + kk);
            ws2[(kk+0)*WS2_PITCH + c] = pk2(v.x, v.x);
            ws2[(kk+1)*WS2_PITCH + c] = pk2(v.y, v.y);
            ws2[(kk+2)*WS2_PITCH + c] = pk2(v.z, v.z);
            ws2[(kk+3)*WS2_PITCH + c] = pk2(v.w, v.w);
        }
        // stage hist chunk k-major: as2[k][r] = hist[mBase+r][kc+k]
        for (int i = tid; i < 1024; i += 256) {
            int r = i >> 3, kk = (i & 7) << 2;
            float4 v = *(const float4*)(g_hist + (mBase + r) * R_SZ + kc + kk);
            as2[(kk+0)*AS_PITCH + r] = v.x; as2[(kk+1)*AS_PITCH + r] = v.y;
            as2[(kk+2)*AS_PITCH + r] = v.z; as2[(kk+3)*AS_PITCH + r] = v.w;
        }
        __syncthreads();

        #pragma unroll 8
        for (int k = 0; k < 32; ++k) {
            ulonglong2 w0 = *(const ulonglong2*)(ws2 + k*WS2_PITCH + c0);      // (c0),(c1) dup
            ulonglong2 w1 = *(const ulonglong2*)(ws2 + k*WS2_PITCH + c0 + 2);  // (c2),(c3) dup
            #pragma unroll
            for (int rp = 0; rp < 4; ++rp) {
                float2 xv = *(const float2*)(as2 + k*AS_PITCH + rp*32 + r0);
                ull xp = pk2(xv.x, xv.y);   // register-pair alias (free)
                acc[rp][0] = fma2(xp, w0.x, acc[rp][0]);
                acc[rp][1] = fma2(xp, w0.y, acc[rp][1]);
                acc[rp][2] = fma2(xp, w1.x, acc[rp][2]);
                acc[rp][3] = fma2(xp, w1.y, acc[rp][3]);
            }
        }
    }

    float bv[4];
    #pragma unroll
    for (int j = 0; j < 4; ++j) bv[j] = brd[C0 + c0 + j];

    #pragma unroll
    for (int rp = 0; rp < 4; ++rp) {
        float lo[4], hi[4];
        #pragma unroll
        for (int j = 0; j < 4; ++j) upk2(lo[j], hi[j], acc[rp][j]);
        #pragma unroll
        for (int h = 0; h < 2; ++h) {
            size_t m = mBase + rp*32 + r0 + h;
            int b = (int)(m & 255), t = (int)(m >> 8);
            float* o = out + (size_t)b * (S_LEN * D_SZ) + (size_t)t * D_SZ + C0 + c0;
            float* src = h ? hi : lo;
            *(float4*)(o) = make_float4(__fadd_rn(src[0], bv[0]), __fadd_rn(src[1], bv[1]),
                                        __fadd_rn(src[2], bv[2]), __fadd_rn(src[3], bv[3]));
        }
    }
}

// ============ Final loss reduce ============
__global__ void reduce_kernel(float* __restrict__ out, int out_size)
{
    if (threadIdx.x != 0 || blockIdx.x != 0) return;
    double a = 0.0, b = 0.0;
    for (int i = 0; i < 8; ++i)   a += g_pc_part[i];
    for (int i = 0; i < 128; ++i) b += g_mse_part[i];
    a /= (double)(B_SZ * D_SZ);
    b /= (double)(B_SZ * R_SZ);
    size_t base = (size_t)B_SZ * S_LEN * D_SZ;
    if ((size_t)out_size >= base + 2) {
        out[base]     = (float)a;
        out[base + 1] = (float)b;
    }
}

extern "C" void kernel_launch(void* const* d_in, const int* in_sizes, int n_in,
                              void* d_out, int out_size)
{
    const float* inputs = (const float*)d_in[0];
    const float* om_in  = (const float*)d_in[1];
    const float* ga_in  = (const float*)d_in[2];
    const float* al_in  = (const float*)d_in[3];
    const float* Wp     = (const float*)d_in[4];
    const float* bp     = (const float*)d_in[5];
    const float* om_r   = (const float*)d_in[6];
    const float* ga_r   = (const float*)d_in[7];
    const float* al_r   = (const float*)d_in[8];
    const float* om_o   = (const float*)d_in[9];
    const float* ga_o   = (const float*)d_in[10];
    const float* al_o   = (const float*)d_in[11];
    const float* Wr     = (const float*)d_in[12];
    const float* brd    = (const float*)d_in[13];
    float* out = (float*)d_out;

    cudaFuncSetAttribute(phaseA_kernel,
        cudaFuncAttributeMaxDynamicSharedMemorySize, 163840);

    dim3 gA(16, 8);
    phaseA_kernel<<<gA, 256, 163840>>>(inputs, om_in, ga_in, al_in, Wp, bp,
                                       om_r, ga_r, al_r, om_o, ga_o, al_o);
    dim3 gB(1024, 2);
    gemm2_kernel<<<gB, 256>>>(Wr, brd, out);
    reduce_kernel<<<1, 1>>>(out, out_size);
}

// round 14
// speedup vs baseline: 1.8640x; 1.8640x over previous
#include <cuda_runtime.h>
#include <cstdint>
#include <cstddef>

typedef unsigned long long ull;

#define S_LEN 512
#define B_SZ  256
#define D_SZ  128
#define R_SZ  2048

__device__ float  g_hist[(size_t)S_LEN * B_SZ * R_SZ];
__device__ double g_pc_part[8];
__device__ double g_mse_part[128];

__device__ __forceinline__ ull pk2(float lo, float hi) {
    ull r; asm("mov.b64 %0, {%1,%2};" : "=l"(r) : "f"(lo), "f"(hi)); return r;
}
__device__ __forceinline__ void upk2(float& lo, float& hi, ull v) {
    asm("mov.b64 {%0,%1}, %2;" : "=f"(lo), "=f"(hi) : "l"(v));
}
__device__ __forceinline__ ull fma2(ull a, ull b, ull c) {
    ull d; asm("fma.rn.f32x2 %0, %1, %2, %3;" : "=l"(d) : "l"(a), "l"(b), "l"(c)); return d;
}
__device__ __forceinline__ float clip5(float v) { return fminf(fmaxf(v, -5.f), 5.f); }

// XLA:GPU-contracted oscillator step (matched recipe — DO NOT CHANGE)
__device__ __forceinline__ float osc_upd(float f, float& x, float& y,
                                         float a, float g2, float w2) {
    float gy = __fmul_rn(g2, y);
    float ac = fmaf(-w2, x, fmaf(a, f, -gy));
    float xn = clip5(fmaf(0.5f, y, x));
    float yn = clip5(fmaf(0.5f, ac, y));
    x = xn; y = yn;
    return xn;
}

// ============ Phase A: persistent recurrence ============
// Grid (16 col-blocks, 8 row-blocks), 256 threads. Thread tile 4r x 4c.
// smem: wt[128][128] floats (64KB) + double-buffered xs[2][128 d][32 rows] (2x16KB).
// Inner loop software-pipelined: loads for d+2 issued while computing d.
__global__ void __launch_bounds__(256, 1) phaseA_kernel(
    const float* __restrict__ inputs,
    const float* __restrict__ om_in, const float* __restrict__ ga_in, const float* __restrict__ al_in,
    const float* __restrict__ Wp,    const float* __restrict__ bp,
    const float* __restrict__ om_r,  const float* __restrict__ ga_r,  const float* __restrict__ al_r,
    const float* __restrict__ om_o,  const float* __restrict__ ga_o,  const float* __restrict__ al_o)
{
    const int cb  = blockIdx.x;   // 0..15 reservoir col block
    const int rb  = blockIdx.y;   // 0..7  batch row block
    const int tid = threadIdx.x;

    extern __shared__ float smem[];
    float* wt  = smem;                    // [128 d][128 c]
    float* xs0 = smem + 128 * 128;        // [128 d][32 rows]
    float* xs1 = xs0 + 128 * 32;

    __shared__ float  pa[128], pg[128], pw[128];
    __shared__ double redd[256];

    // stage W_proj tile transposed: wt[d][c] = Wp[cb*128+c][d]
    for (int i = tid; i < 4096; i += 256) {
        int c = i >> 5, d0 = (i & 31) << 2;
        float4 v = *(const float4*)(Wp + ((size_t)(cb * 128 + c)) * D_SZ + d0);
        wt[(d0+0)*128 + c] = v.x; wt[(d0+1)*128 + c] = v.y;
        wt[(d0+2)*128 + c] = v.z; wt[(d0+3)*128 + c] = v.w;
    }
    if (tid < 128) {
        pa[tid] = al_in[tid];
        pg[tid] = __fmul_rn(2.f, fabsf(ga_in[tid]));
        float o = fabsf(om_in[tid]); pw[tid] = __fmul_rn(o, o);
    }

    // input-oscillator mapping: row = lane, 16 consecutive d per warp
    const int irow = tid & 31;            // 0..31
    const int dch  = (tid >> 5) << 4;     // warp*16
    const int gb_i = rb * 32 + irow;

    // GEMM mapping: 4 rows x 4 cols per thread (row-pair f32x2 packing)
    const int lane = tid & 31, warp = tid >> 5;
    const int r0 = (lane & 7) << 2;
    const int c0 = warp * 16 + ((lane >> 3) << 2);

    float par[4], pgr[4], pwr[4], pao[4], pgo[4], pwo[4], bpv[4];
    {
        int rbase = cb * 128 + c0;
        #pragma unroll
        for (int j = 0; j < 4; ++j) {
            par[j] = al_r[rbase+j];
            pgr[j] = __fmul_rn(2.f, fabsf(ga_r[rbase+j]));
            float o = fabsf(om_r[rbase+j]); pwr[j] = __fmul_rn(o, o);
            pao[j] = al_o[rbase+j];
            pgo[j] = __fmul_rn(2.f, fabsf(ga_o[rbase+j]));
            float q = fabsf(om_o[rbase+j]); pwo[j] = __fmul_rn(q, q);
            bpv[j] = bp[rbase+j];
        }
    }

    float x_in[16], y_in[16], xr[16], yr[16], xo[16], yo[16];
    #pragma unroll
    for (int k = 0; k < 16; ++k) { x_in[k]=0.f; y_in[k]=0.f; xr[k]=0.f; yr[k]=0.f; xo[k]=0.f; yo[k]=0.f; }

    double lin = 0.0, lmse = 0.0;

    float inpv[16];
    {
        const float* p = inputs + (size_t)gb_i * (S_LEN * D_SZ) + dch;
        #pragma unroll
        for (int q = 0; q < 4; ++q) {
            float4 v = *(const float4*)(p + q*4);
            inpv[q*4]=v.x; inpv[q*4+1]=v.y; inpv[q*4+2]=v.z; inpv[q*4+3]=v.w;
        }
    }
    __syncthreads();   // staging complete before any use

    for (int t = 0; t < S_LEN; ++t) {
        float* xs = (t & 1) ? xs1 : xs0;

        if (t > 0) {
            float ls = 0.f;
            #pragma unroll
            for (int k = 0; k < 16; ++k) { float df = x_in[k]-inpv[k]; ls = fmaf(df, df, ls); }
            lin += (double)ls;
        }
        #pragma unroll
        for (int k = 0; k < 16; ++k) {
            int d = dch + k;
            osc_upd(inpv[k], x_in[k], y_in[k], pa[d], pg[d], pw[d]);
        }
        #pragma unroll
        for (int k = 0; k < 16; ++k)
            xs[(dch + k) * 32 + irow] = x_in[k];
        __syncthreads();   // the ONLY barrier per step (double-buffered xs)

        {   // prefetch next input slice under the GEMM
            int tn = (t < S_LEN-1) ? t+1 : t;
            const float* p = inputs + (size_t)gb_i * (S_LEN*D_SZ) + (size_t)tn * D_SZ + dch;
            #pragma unroll
            for (int q = 0; q < 4; ++q) {
                float4 v = *(const float4*)(p + q*4);
                inpv[q*4]=v.x; inpv[q*4+1]=v.y; inpv[q*4+2]=v.z; inpv[q*4+3]=v.w;
            }
        }

        // GEMM1 tile: proj = x_in @ Wp^T  (software-pipelined)
        // acc[rp][j] packs rows (r0+2rp, r0+2rp+1) for col c0+j.
        // Per element: acc=0, ascending-d fma chain — identical math.
        ull acc[2][4];
        #pragma unroll
        for (int j = 0; j < 4; ++j) { acc[0][j] = 0ull; acc[1][j] = 0ull; }

        // preload d=0,1
        float4 xa = *(const float4*)(xs + 0*32 + r0);
        float4 xb = *(const float4*)(xs + 1*32 + r0);
        float4 wa = *(const float4*)(wt + 0*128 + c0);
        float4 wb = *(const float4*)(wt + 1*128 + c0);

        #pragma unroll 8
        for (int d = 0; d < 128; d += 2) {
            float4 xa_c = xa, xb_c = xb, wa_c = wa, wb_c = wb;
            int dn = (d + 2 < 128) ? d + 2 : 0;   // wrap: harmless redundant load
            xa = *(const float4*)(xs + dn*32 + r0);
            xb = *(const float4*)(xs + (dn+1)*32 + r0);
            wa = *(const float4*)(wt + dn*128 + c0);
            wb = *(const float4*)(wt + (dn+1)*128 + c0);

            ull xa0 = pk2(xa_c.x, xa_c.y), xa1 = pk2(xa_c.z, xa_c.w);
            ull xb0 = pk2(xb_c.x, xb_c.y), xb1 = pk2(xb_c.z, xb_c.w);
            float wav[4] = {wa_c.x, wa_c.y, wa_c.z, wa_c.w};
            float wbv[4] = {wb_c.x, wb_c.y, wb_c.z, wb_c.w};
            #pragma unroll
            for (int j = 0; j < 4; ++j) {
                ull wda = pk2(wav[j], wav[j]);
                ull wdb = pk2(wbv[j], wbv[j]);
                acc[0][j] = fma2(xa0, wda, acc[0][j]);
                acc[1][j] = fma2(xa1, wda, acc[1][j]);
                acc[0][j] = fma2(xb0, wdb, acc[0][j]);
                acc[1][j] = fma2(xb1, wdb, acc[1][j]);
            }
        }

        // unpack: element (i row, j col), i = 2*rp + half
        float fv[4][4];
        #pragma unroll
        for (int rp = 0; rp < 2; ++rp)
            #pragma unroll
            for (int j = 0; j < 4; ++j) {
                float lo, hi; upk2(lo, hi, acc[rp][j]);
                fv[2*rp][j] = lo; fv[2*rp+1][j] = hi;
            }

        float ls2 = 0.f;
        #pragma unroll
        for (int i = 0; i < 4; ++i) {
            #pragma unroll
            for (int j = 0; j < 4; ++j) {
                int k = i*4 + j;
                float f = __fadd_rn(fv[i][j], bpv[j]);   // bias after dot (matched)
                float xrn = osc_upd(f,   xr[k], yr[k], par[j], pgr[j], pwr[j]);
                float xon = osc_upd(xrn, xo[k], yo[k], pao[j], pgo[j], pwo[j]);
                float df = xon - xrn;
                ls2 = fmaf(df, df, ls2);
            }
        }
        lmse += (double)ls2;

        size_t hb = ((size_t)t * B_SZ + rb*32 + r0) * R_SZ + cb*128 + c0;
        #pragma unroll
        for (int i = 0; i < 4; ++i)
            *(float4*)(g_hist + hb + (size_t)i * R_SZ) =
                make_float4(xo[i*4], xo[i*4+1], xo[i*4+2], xo[i*4+3]);
    }

    __syncthreads();
    redd[tid] = lin; __syncthreads();
    for (int s = 128; s > 0; s >>= 1) { if (tid < s) redd[tid] += redd[tid+s]; __syncthreads(); }
    if (tid == 0 && cb == 0) g_pc_part[rb] = redd[0];
    __syncthreads();
    redd[tid] = lmse; __syncthreads();
    for (int s = 128; s > 0; s >>= 1) { if (tid < s) redd[tid] += redd[tid+s]; __syncthreads(); }
    if (tid == 0) g_mse_part[rb*16 + cb] = redd[0];
}

// ============ Phase B: preds = hist @ W_read^T + b_read ============
// CTA tile: 128 rows x 64 cols. Grid (1024, 2), 256 threads.
// Thread: 8 rows (4 row-pairs spaced 32) x 4 cols. k-major smem staging.
#define AS_PITCH 130
#define WS_PITCH 68
__global__ void __launch_bounds__(256, 2) gemm2_kernel(
    const float* __restrict__ Wr, const float* __restrict__ brd, float* __restrict__ out)
{
    __shared__ __align__(16) float ws[32 * WS_PITCH];    // ws[k][c], c<64
    __shared__ __align__(16) float as2[32 * AS_PITCH];   // as2[k][r], r<128

    const int tid = threadIdx.x;
    const int lane = tid & 31, warp = tid >> 5;
    const int rg = lane & 15, cg = lane >> 4;
    const int r0 = rg * 2;                   // rows r0 + rp*32 + {0,1}
    const int c0 = warp * 8 + cg * 4;        // local col base (0..60 within 64)
    const int C0 = blockIdx.y * 64;
    const size_t mBase = (size_t)blockIdx.x * 128;

    ull acc[4][4];
    #pragma unroll
    for (int rp = 0; rp < 4; ++rp)
        #pragma unroll
        for (int j = 0; j < 4; ++j) acc[rp][j] = 0ull;

    for (int kc = 0; kc < R_SZ; kc += 32) {
        __syncthreads();
        // stage W chunk k-major: ws[k][c] = Wr[(C0+c)*R + kc+k]
        for (int i = tid; i < 512; i += 256) {
            int c = i >> 3, kk = (i & 7) << 2;
            float4 v = *(const float4*)(Wr + (size_t)(C0 + c) * R_SZ + kc + kk);
            ws[(kk+0)*WS_PITCH + c] = v.x; ws[(kk+1)*WS_PITCH + c] = v.y;
            ws[(kk+2)*WS_PITCH + c] = v.z; ws[(kk+3)*WS_PITCH + c] = v.w;
        }
        // stage hist chunk k-major: as2[k][r] = hist[mBase+r][kc+k]
        for (int i = tid; i < 1024; i += 256) {
            int r = i >> 3, kk = (i & 7) << 2;
            float4 v = *(const float4*)(g_hist + (mBase + r) * R_SZ + kc + kk);
            as2[(kk+0)*AS_PITCH + r] = v.x; as2[(kk+1)*AS_PITCH + r] = v.y;
            as2[(kk+2)*AS_PITCH + r] = v.z; as2[(kk+3)*AS_PITCH + r] = v.w;
        }
        __syncthreads();

        #pragma unroll 8
        for (int k = 0; k < 32; ++k) {
            float4 wv = *(const float4*)(ws + k*WS_PITCH + c0);
            ull wd0 = pk2(wv.x, wv.x), wd1 = pk2(wv.y, wv.y);
            ull wd2 = pk2(wv.z, wv.z), wd3 = pk2(wv.w, wv.w);
            #pragma unroll
            for (int rp = 0; rp < 4; ++rp) {
                float2 xv = *(const float2*)(as2 + k*AS_PITCH + rp*32 + r0);
                ull xp = pk2(xv.x, xv.y);
                acc[rp][0] = fma2(xp, wd0, acc[rp][0]);
                acc[rp][1] = fma2(xp, wd1, acc[rp][1]);
                acc[rp][2] = fma2(xp, wd2, acc[rp][2]);
                acc[rp][3] = fma2(xp, wd3, acc[rp][3]);
            }
        }
    }

    float bv[4];
    #pragma unroll
    for (int j = 0; j < 4; ++j) bv[j] = brd[C0 + c0 + j];

    #pragma unroll
    for (int rp = 0; rp < 4; ++rp) {
        float lo[4], hi[4];
        #pragma unroll
        for (int j = 0; j < 4; ++j) upk2(lo[j], hi[j], acc[rp][j]);
        #pragma unroll
        for (int h = 0; h < 2; ++h) {
            size_t m = mBase + rp*32 + r0 + h;
            int b = (int)(m & 255), t = (int)(m >> 8);
            float* o = out + (size_t)b * (S_LEN * D_SZ) + (size_t)t * D_SZ + C0 + c0;
            float* src = h ? hi : lo;
            *(float4*)(o) = make_float4(__fadd_rn(src[0], bv[0]), __fadd_rn(src[1], bv[1]),
                                        __fadd_rn(src[2], bv[2]), __fadd_rn(src[3], bv[3]));
        }
    }
}

// ============ Final loss reduce ============
__global__ void reduce_kernel(float* __restrict__ out, int out_size)
{
    if (threadIdx.x != 0 || blockIdx.x != 0) return;
    double a = 0.0, b = 0.0;
    for (int i = 0; i < 8; ++i)   a += g_pc_part[i];
    for (int i = 0; i < 128; ++i) b += g_mse_part[i];
    a /= (double)(B_SZ * D_SZ);
    b /= (double)(B_SZ * R_SZ);
    size_t base = (size_t)B_SZ * S_LEN * D_SZ;
    if ((size_t)out_size >= base + 2) {
        out[base]     = (float)a;
        out[base + 1] = (float)b;
    }
}

extern "C" void kernel_launch(void* const* d_in, const int* in_sizes, int n_in,
                              void* d_out, int out_size)
{
    const float* inputs = (const float*)d_in[0];
    const float* om_in  = (const float*)d_in[1];
    const float* ga_in  = (const float*)d_in[2];
    const float* al_in  = (const float*)d_in[3];
    const float* Wp     = (const float*)d_in[4];
    const float* bp     = (const float*)d_in[5];
    const float* om_r   = (const float*)d_in[6];
    const float* ga_r   = (const float*)d_in[7];
    const float* al_r   = (const float*)d_in[8];
    const float* om_o   = (const float*)d_in[9];
    const float* ga_o   = (const float*)d_in[10];
    const float* al_o   = (const float*)d_in[11];
    const float* Wr     = (const float*)d_in[12];
    const float* brd    = (const float*)d_in[13];
    float* out = (float*)d_out;

    cudaFuncSetAttribute(phaseA_kernel,
        cudaFuncAttributeMaxDynamicSharedMemorySize, 98304);

    dim3 gA(16, 8);
    phaseA_kernel<<<gA, 256, 98304>>>(inputs, om_in, ga_in, al_in, Wp, bp,
                                      om_r, ga_r, al_r, om_o, ga_o, al_o);
    dim3 gB(1024, 2);
    gemm2_kernel<<<gB, 256>>>(Wr, brd, out);
    reduce_kernel<<<1, 1>>>(out, out_size);
}

// round 15
// speedup vs baseline: 1.9225x; 1.0314x over previous
#include <cuda_runtime.h>
#include <cstdint>
#include <cstddef>

typedef unsigned long long ull;

#define S_LEN 512
#define B_SZ  256
#define D_SZ  128
#define R_SZ  2048

__device__ float  g_hist[(size_t)S_LEN * B_SZ * R_SZ];
__device__ double g_pc_part[16];
__device__ double g_mse_part[256];

__device__ __forceinline__ ull pk2(float lo, float hi) {
    ull r; asm("mov.b64 %0, {%1,%2};" : "=l"(r) : "f"(lo), "f"(hi)); return r;
}
__device__ __forceinline__ void upk2(float& lo, float& hi, ull v) {
    asm("mov.b64 {%0,%1}, %2;" : "=f"(lo), "=f"(hi) : "l"(v));
}
__device__ __forceinline__ ull fma2(ull a, ull b, ull c) {
    ull d; asm("fma.rn.f32x2 %0, %1, %2, %3;" : "=l"(d) : "l"(a), "l"(b), "l"(c)); return d;
}
__device__ __forceinline__ float clip5(float v) { return fminf(fmaxf(v, -5.f), 5.f); }

// XLA:GPU-contracted oscillator step (matched recipe — DO NOT CHANGE)
__device__ __forceinline__ float osc_upd(float f, float& x, float& y,
                                         float a, float g2, float w2) {
    float gy = __fmul_rn(g2, y);
    float ac = fmaf(-w2, x, fmaf(a, f, -gy));
    float xn = clip5(fmaf(0.5f, y, x));
    float yn = clip5(fmaf(0.5f, ac, y));
    x = xn; y = yn;
    return xn;
}

// ============ Phase A: persistent recurrence ============
// Grid (16 col-blocks, 16 row-blocks of 16 rows), 128 threads, 2 CTAs/SM.
// Thread tile 4r x 4c (unchanged). smem per CTA: wt[128][128] (64KB) +
// double-buffered xs[2][128 d][16 rows] (2x8KB) = 80KB.
__global__ void __launch_bounds__(128, 2) phaseA_kernel(
    const float* __restrict__ inputs,
    const float* __restrict__ om_in, const float* __restrict__ ga_in, const float* __restrict__ al_in,
    const float* __restrict__ Wp,    const float* __restrict__ bp,
    const float* __restrict__ om_r,  const float* __restrict__ ga_r,  const float* __restrict__ al_r,
    const float* __restrict__ om_o,  const float* __restrict__ ga_o,  const float* __restrict__ al_o)
{
    const int cb  = blockIdx.x;   // 0..15 reservoir col block
    const int rb  = blockIdx.y;   // 0..15 batch row block (16 rows)
    const int tid = threadIdx.x;

    extern __shared__ float smem[];
    float* wt  = smem;                    // [128 d][128 c]
    float* xs0 = smem + 128 * 128;        // [128 d][16 rows]
    float* xs1 = xs0 + 128 * 16;

    __shared__ float  pa[128], pg[128], pw[128];
    __shared__ double redd[128];

    // stage W_proj tile transposed: wt[d][c] = Wp[cb*128+c][d]
    for (int i = tid; i < 4096; i += 128) {
        int c = i >> 5, d0 = (i & 31) << 2;
        float4 v = *(const float4*)(Wp + ((size_t)(cb * 128 + c)) * D_SZ + d0);
        wt[(d0+0)*128 + c] = v.x; wt[(d0+1)*128 + c] = v.y;
        wt[(d0+2)*128 + c] = v.z; wt[(d0+3)*128 + c] = v.w;
    }
    {
        pa[tid] = al_in[tid];
        pg[tid] = __fmul_rn(2.f, fabsf(ga_in[tid]));
        float o = fabsf(om_in[tid]); pw[tid] = __fmul_rn(o, o);
    }

    // input-oscillator mapping: 16 rows x 8 d-chunks of 16
    const int irow = tid & 15;            // 0..15
    const int dch  = (tid >> 4) << 4;     // chunk*16
    const int gb_i = rb * 16 + irow;

    // GEMM mapping: 4 rows x 4 cols per thread (row-pair f32x2 packing)
    const int lane = tid & 31, warp = tid >> 5;
    const int r0 = (lane & 3) << 2;                 // 0,4,8,12
    const int c0 = warp * 32 + ((lane >> 2) << 2);  // 8 col-groups x 4

    float par[4], pgr[4], pwr[4], pao[4], pgo[4], pwo[4], bpv[4];
    {
        int rbase = cb * 128 + c0;
        #pragma unroll
        for (int j = 0; j < 4; ++j) {
            par[j] = al_r[rbase+j];
            pgr[j] = __fmul_rn(2.f, fabsf(ga_r[rbase+j]));
            float o = fabsf(om_r[rbase+j]); pwr[j] = __fmul_rn(o, o);
            pao[j] = al_o[rbase+j];
            pgo[j] = __fmul_rn(2.f, fabsf(ga_o[rbase+j]));
            float q = fabsf(om_o[rbase+j]); pwo[j] = __fmul_rn(q, q);
            bpv[j] = bp[rbase+j];
        }
    }

    float x_in[16], y_in[16], xr[16], yr[16], xo[16], yo[16];
    #pragma unroll
    for (int k = 0; k < 16; ++k) { x_in[k]=0.f; y_in[k]=0.f; xr[k]=0.f; yr[k]=0.f; xo[k]=0.f; yo[k]=0.f; }

    double lin = 0.0, lmse = 0.0;

    float inpv[16];
    {
        const float* p = inputs + (size_t)gb_i * (S_LEN * D_SZ) + dch;
        #pragma unroll
        for (int q = 0; q < 4; ++q) {
            float4 v = *(const float4*)(p + q*4);
            inpv[q*4]=v.x; inpv[q*4+1]=v.y; inpv[q*4+2]=v.z; inpv[q*4+3]=v.w;
        }
    }
    __syncthreads();   // staging complete before any use

    for (int t = 0; t < S_LEN; ++t) {
        float* xs = (t & 1) ? xs1 : xs0;

        if (t > 0) {
            float ls = 0.f;
            #pragma unroll
            for (int k = 0; k < 16; ++k) { float df = x_in[k]-inpv[k]; ls = fmaf(df, df, ls); }
            lin += (double)ls;
        }
        {   // vectorized param re-load (value-identical to scalar reads)
            float pav[16], pgv[16], pwv[16];
            #pragma unroll
            for (int q = 0; q < 4; ++q) {
                float4 a4 = *(const float4*)(pa + dch + q*4);
                float4 g4 = *(const float4*)(pg + dch + q*4);
                float4 w4 = *(const float4*)(pw + dch + q*4);
                pav[q*4]=a4.x; pav[q*4+1]=a4.y; pav[q*4+2]=a4.z; pav[q*4+3]=a4.w;
                pgv[q*4]=g4.x; pgv[q*4+1]=g4.y; pgv[q*4+2]=g4.z; pgv[q*4+3]=g4.w;
                pwv[q*4]=w4.x; pwv[q*4+1]=w4.y; pwv[q*4+2]=w4.z; pwv[q*4+3]=w4.w;
            }
            #pragma unroll
            for (int k = 0; k < 16; ++k)
                osc_upd(inpv[k], x_in[k], y_in[k], pav[k], pgv[k], pwv[k]);
        }
        #pragma unroll
        for (int k = 0; k < 16; ++k)
            xs[(dch + k) * 16 + irow] = x_in[k];
        __syncthreads();   // the ONLY barrier per step (double-buffered xs)

        {   // prefetch next input slice under the GEMM
            int tn = (t < S_LEN-1) ? t+1 : t;
            const float* p = inputs + (size_t)gb_i * (S_LEN*D_SZ) + (size_t)tn * D_SZ + dch;
            #pragma unroll
            for (int q = 0; q < 4; ++q) {
                float4 v = *(const float4*)(p + q*4);
                inpv[q*4]=v.x; inpv[q*4+1]=v.y; inpv[q*4+2]=v.z; inpv[q*4+3]=v.w;
            }
        }

        // GEMM1 tile: proj = x_in @ Wp^T
        // acc[rp][j] packs rows (r0+2rp, r0+2rp+1) for col c0+j.
        // Per element: acc=0, ascending-d fma chain — identical math.
        ull acc[2][4];
        #pragma unroll
        for (int j = 0; j < 4; ++j) { acc[0][j] = 0ull; acc[1][j] = 0ull; }

        #pragma unroll 8
        for (int d = 0; d < 128; d += 2) {
            float4 xa = *(const float4*)(xs + d*16 + r0);        // rows r0..r0+3 @ d
            float4 xb = *(const float4*)(xs + (d+1)*16 + r0);    // rows r0..r0+3 @ d+1
            float4 wa = *(const float4*)(wt + d*128 + c0);       // cols c0..c0+3 @ d
            float4 wb = *(const float4*)(wt + (d+1)*128 + c0);
            ull xa0 = pk2(xa.x, xa.y), xa1 = pk2(xa.z, xa.w);
            ull xb0 = pk2(xb.x, xb.y), xb1 = pk2(xb.z, xb.w);
            float wav[4] = {wa.x, wa.y, wa.z, wa.w};
            float wbv[4] = {wb.x, wb.y, wb.z, wb.w};
            #pragma unroll
            for (int j = 0; j < 4; ++j) {
                ull wda = pk2(wav[j], wav[j]);
                ull wdb = pk2(wbv[j], wbv[j]);
                acc[0][j] = fma2(xa0, wda, acc[0][j]);
                acc[1][j] = fma2(xa1, wda, acc[1][j]);
                acc[0][j] = fma2(xb0, wdb, acc[0][j]);
                acc[1][j] = fma2(xb1, wdb, acc[1][j]);
            }
        }

        // unpack: element (i row, j col), i = 2*rp + half
        float fv[4][4];
        #pragma unroll
        for (int rp = 0; rp < 2; ++rp)
            #pragma unroll
            for (int j = 0; j < 4; ++j) {
                float lo, hi; upk2(lo, hi, acc[rp][j]);
                fv[2*rp][j] = lo; fv[2*rp+1][j] = hi;
            }

        float ls2 = 0.f;
        #pragma unroll
        for (int i = 0; i < 4; ++i) {
            #pragma unroll
            for (int j = 0; j < 4; ++j) {
                int k = i*4 + j;
                float f = __fadd_rn(fv[i][j], bpv[j]);   // bias after dot (matched)
                float xrn = osc_upd(f,   xr[k], yr[k], par[j], pgr[j], pwr[j]);
                float xon = osc_upd(xrn, xo[k], yo[k], pao[j], pgo[j], pwo[j]);
                float df = xon - xrn;
                ls2 = fmaf(df, df, ls2);
            }
        }
        lmse += (double)ls2;

        size_t hb = ((size_t)t * B_SZ + rb*16 + r0) * R_SZ + cb*128 + c0;
        #pragma unroll
        for (int i = 0; i < 4; ++i)
            *(float4*)(g_hist + hb + (size_t)i * R_SZ) =
                make_float4(xo[i*4], xo[i*4+1], xo[i*4+2], xo[i*4+3]);
    }

    __syncthreads();
    redd[tid] = lin; __syncthreads();
    for (int s = 64; s > 0; s >>= 1) { if (tid < s) redd[tid] += redd[tid+s]; __syncthreads(); }
    if (tid == 0 && cb == 0) g_pc_part[rb] = redd[0];
    __syncthreads();
    redd[tid] = lmse; __syncthreads();
    for (int s = 64; s > 0; s >>= 1) { if (tid < s) redd[tid] += redd[tid+s]; __syncthreads(); }
    if (tid == 0) g_mse_part[rb*16 + cb] = redd[0];
}

// ============ Phase B: preds = hist @ W_read^T + b_read ============
// CTA tile: 128 rows x 64 cols. Grid (1024, 2), 256 threads.
// Thread: 8 rows (4 row-pairs spaced 32) x 4 cols. k-major smem staging.
#define AS_PITCH 130
#define WS_PITCH 68
__global__ void __launch_bounds__(256, 2) gemm2_kernel(
    const float* __restrict__ Wr, const float* __restrict__ brd, float* __restrict__ out)
{
    __shared__ __align__(16) float ws[32 * WS_PITCH];    // ws[k][c], c<64
    __shared__ __align__(16) float as2[32 * AS_PITCH];   // as2[k][r], r<128

    const int tid = threadIdx.x;
    const int lane = tid & 31, warp = tid >> 5;
    const int rg = lane & 15, cg = lane >> 4;
    const int r0 = rg * 2;                   // rows r0 + rp*32 + {0,1}
    const int c0 = warp * 8 + cg * 4;        // local col base (0..60 within 64)
    const int C0 = blockIdx.y * 64;
    const size_t mBase = (size_t)blockIdx.x * 128;

    ull acc[4][4];
    #pragma unroll
    for (int rp = 0; rp < 4; ++rp)
        #pragma unroll
        for (int j = 0; j < 4; ++j) acc[rp][j] = 0ull;

    for (int kc = 0; kc < R_SZ; kc += 32) {
        __syncthreads();
        // stage W chunk k-major: ws[k][c] = Wr[(C0+c)*R + kc+k]
        for (int i = tid; i < 512; i += 256) {
            int c = i >> 3, kk = (i & 7) << 2;
            float4 v = *(const float4*)(Wr + (size_t)(C0 + c) * R_SZ + kc + kk);
            ws[(kk+0)*WS_PITCH + c] = v.x; ws[(kk+1)*WS_PITCH + c] = v.y;
            ws[(kk+2)*WS_PITCH + c] = v.z; ws[(kk+3)*WS_PITCH + c] = v.w;
        }
        // stage hist chunk k-major: as2[k][r] = hist[mBase+r][kc+k]
        for (int i = tid; i < 1024; i += 256) {
            int r = i >> 3, kk = (i & 7) << 2;
            float4 v = *(const float4*)(g_hist + (mBase + r) * R_SZ + kc + kk);
            as2[(kk+0)*AS_PITCH + r] = v.x; as2[(kk+1)*AS_PITCH + r] = v.y;
            as2[(kk+2)*AS_PITCH + r] = v.z; as2[(kk+3)*AS_PITCH + r] = v.w;
        }
        __syncthreads();

        #pragma unroll 8
        for (int k = 0; k < 32; ++k) {
            float4 wv = *(const float4*)(ws + k*WS_PITCH + c0);
            ull wd0 = pk2(wv.x, wv.x), wd1 = pk2(wv.y, wv.y);
            ull wd2 = pk2(wv.z, wv.z), wd3 = pk2(wv.w, wv.w);
            #pragma unroll
            for (int rp = 0; rp < 4; ++rp) {
                float2 xv = *(const float2*)(as2 + k*AS_PITCH + rp*32 + r0);
                ull xp = pk2(xv.x, xv.y);
                acc[rp][0] = fma2(xp, wd0, acc[rp][0]);
                acc[rp][1] = fma2(xp, wd1, acc[rp][1]);
                acc[rp][2] = fma2(xp, wd2, acc[rp][2]);
                acc[rp][3] = fma2(xp, wd3, acc[rp][3]);
            }
        }
    }

    float bv[4];
    #pragma unroll
    for (int j = 0; j < 4; ++j) bv[j] = brd[C0 + c0 + j];

    #pragma unroll
    for (int rp = 0; rp < 4; ++rp) {
        float lo[4], hi[4];
        #pragma unroll
        for (int j = 0; j < 4; ++j) upk2(lo[j], hi[j], acc[rp][j]);
        #pragma unroll
        for (int h = 0; h < 2; ++h) {
            size_t m = mBase + rp*32 + r0 + h;
            int b = (int)(m & 255), t = (int)(m >> 8);
            float* o = out + (size_t)b * (S_LEN * D_SZ) + (size_t)t * D_SZ + C0 + c0;
            float* src = h ? hi : lo;
            *(float4*)(o) = make_float4(__fadd_rn(src[0], bv[0]), __fadd_rn(src[1], bv[1]),
                                        __fadd_rn(src[2], bv[2]), __fadd_rn(src[3], bv[3]));
        }
    }
}

// ============ Final loss reduce ============
__global__ void reduce_kernel(float* __restrict__ out, int out_size)
{
    if (threadIdx.x != 0 || blockIdx.x != 0) return;
    double a = 0.0, b = 0.0;
    for (int i = 0; i < 16; ++i)  a += g_pc_part[i];
    for (int i = 0; i < 256; ++i) b += g_mse_part[i];
    a /= (double)(B_SZ * D_SZ);
    b /= (double)(B_SZ * R_SZ);
    size_t base = (size_t)B_SZ * S_LEN * D_SZ;
    if ((size_t)out_size >= base + 2) {
        out[base]     = (float)a;
        out[base + 1] = (float)b;
    }
}

extern "C" void kernel_launch(void* const* d_in, const int* in_sizes, int n_in,
                              void* d_out, int out_size)
{
    const float* inputs = (const float*)d_in[0];
    const float* om_in  = (const float*)d_in[1];
    const float* ga_in  = (const float*)d_in[2];
    const float* al_in  = (const float*)d_in[3];
    const float* Wp     = (const float*)d_in[4];
    const float* bp     = (const float*)d_in[5];
    const float* om_r   = (const float*)d_in[6];
    const float* ga_r   = (const float*)d_in[7];
    const float* al_r   = (const float*)d_in[8];
    const float* om_o   = (const float*)d_in[9];
    const float* ga_o   = (const float*)d_in[10];
    const float* al_o   = (const float*)d_in[11];
    const float* Wr     = (const float*)d_in[12];
    const float* brd    = (const float*)d_in[13];
    float* out = (float*)d_out;

    cudaFuncSetAttribute(phaseA_kernel,
        cudaFuncAttributeMaxDynamicSharedMemorySize, 81920);

    dim3 gA(16, 16);
    phaseA_kernel<<<gA, 128, 81920>>>(inputs, om_in, ga_in, al_in, Wp, bp,
                                      om_r, ga_r, al_r, om_o, ga_o, al_o);
    dim3 gB(1024, 2);
    gemm2_kernel<<<gB, 256>>>(Wr, brd, out);
    reduce_kernel<<<1, 1>>>(out, out_size);
}

// round 16
// speedup vs baseline: 2.3645x; 1.2299x over previous
#include <cuda_runtime.h>
#include <cstdint>
#include <cstddef>

typedef unsigned long long ull;

#define S_LEN 512
#define B_SZ  256
#define D_SZ  128
#define R_SZ  2048
#define M_TOT (S_LEN * B_SZ)   // 131072

// hist transposed: g_hist[r][m], m = t*256 + b   (1 GiB)
__device__ float  g_hist[(size_t)R_SZ * M_TOT];
__device__ float  g_WrT[(size_t)R_SZ * D_SZ];    // WrT[k][c]
__device__ double g_pc_part[16];
__device__ double g_mse_part[256];

__device__ __forceinline__ ull pk2(float lo, float hi) {
    ull r; asm("mov.b64 %0, {%1,%2};" : "=l"(r) : "f"(lo), "f"(hi)); return r;
}
__device__ __forceinline__ void upk2(float& lo, float& hi, ull v) {
    asm("mov.b64 {%0,%1}, %2;" : "=f"(lo), "=f"(hi) : "l"(v));
}
__device__ __forceinline__ ull fma2(ull a, ull b, ull c) {
    ull d; asm("fma.rn.f32x2 %0, %1, %2, %3;" : "=l"(d) : "l"(a), "l"(b), "l"(c)); return d;
}
__device__ __forceinline__ float clip5(float v) { return fminf(fmaxf(v, -5.f), 5.f); }
__device__ __forceinline__ uint32_t smem_u32(const void* p) {
    uint32_t a;
    asm("{ .reg .u64 t; cvta.to.shared.u64 t, %1; cvt.u32.u64 %0, t; }" : "=r"(a) : "l"(p));
    return a;
}
__device__ __forceinline__ void cp16(uint32_t s, const void* g) {
    asm volatile("cp.async.cg.shared.global [%0], [%1], 16;" :: "r"(s), "l"(g));
}

// XLA:GPU-contracted oscillator step (matched recipe — DO NOT CHANGE)
__device__ __forceinline__ float osc_upd(float f, float& x, float& y,
                                         float a, float g2, float w2) {
    float gy = __fmul_rn(g2, y);
    float ac = fmaf(-w2, x, fmaf(a, f, -gy));
    float xn = clip5(fmaf(0.5f, y, x));
    float yn = clip5(fmaf(0.5f, ac, y));
    x = xn; y = yn;
    return xn;
}

// ============ W_read transpose: WrT[k][c] = Wr[c][k] ============
__global__ void wrt_kernel(const float* __restrict__ Wr)
{
    __shared__ float tile[32][33];
    int kBase = blockIdx.x * 32, cBase = blockIdx.y * 32;
    int tx = threadIdx.x, ty = threadIdx.y;   // 32 x 8
    #pragma unroll
    for (int q = 0; q < 32; q += 8)
        tile[ty + q][tx] = Wr[(size_t)(cBase + ty + q) * R_SZ + kBase + tx];
    __syncthreads();
    #pragma unroll
    for (int q = 0; q < 32; q += 8)
        g_WrT[(size_t)(kBase + ty + q) * D_SZ + cBase + tx] = tile[tx][ty + q];
}

// ============ Phase A: persistent recurrence ============
// Grid (16 col-blocks, 16 row-blocks of 16 rows), 128 threads, 2 CTAs/SM.
__global__ void __launch_bounds__(128, 2) phaseA_kernel(
    const float* __restrict__ inputs,
    const float* __restrict__ om_in, const float* __restrict__ ga_in, const float* __restrict__ al_in,
    const float* __restrict__ Wp,    const float* __restrict__ bp,
    const float* __restrict__ om_r,  const float* __restrict__ ga_r,  const float* __restrict__ al_r,
    const float* __restrict__ om_o,  const float* __restrict__ ga_o,  const float* __restrict__ al_o)
{
    const int cb  = blockIdx.x;   // 0..15 reservoir col block
    const int rb  = blockIdx.y;   // 0..15 batch row block (16 rows)
    const int tid = threadIdx.x;

    extern __shared__ float smem[];
    float* wt  = smem;                    // [128 d][128 c]
    float* xs0 = smem + 128 * 128;        // [128 d][16 rows]
    float* xs1 = xs0 + 128 * 16;

    __shared__ float  pa[128], pg[128], pw[128];
    __shared__ double redd[128];

    for (int i = tid; i < 4096; i += 128) {
        int c = i >> 5, d0 = (i & 31) << 2;
        float4 v = *(const float4*)(Wp + ((size_t)(cb * 128 + c)) * D_SZ + d0);
        wt[(d0+0)*128 + c] = v.x; wt[(d0+1)*128 + c] = v.y;
        wt[(d0+2)*128 + c] = v.z; wt[(d0+3)*128 + c] = v.w;
    }
    {
        pa[tid] = al_in[tid];
        pg[tid] = __fmul_rn(2.f, fabsf(ga_in[tid]));
        float o = fabsf(om_in[tid]); pw[tid] = __fmul_rn(o, o);
    }

    const int irow = tid & 15;            // 0..15
    const int dch  = (tid >> 4) << 4;     // chunk*16
    const int gb_i = rb * 16 + irow;

    const int lane = tid & 31, warp = tid >> 5;
    const int r0 = (lane & 3) << 2;                 // 0,4,8,12
    const int c0 = warp * 32 + ((lane >> 2) << 2);  // 8 col-groups x 4

    float par[4], pgr[4], pwr[4], pao[4], pgo[4], pwo[4], bpv[4];
    {
        int rbase = cb * 128 + c0;
        #pragma unroll
        for (int j = 0; j < 4; ++j) {
            par[j] = al_r[rbase+j];
            pgr[j] = __fmul_rn(2.f, fabsf(ga_r[rbase+j]));
            float o = fabsf(om_r[rbase+j]); pwr[j] = __fmul_rn(o, o);
            pao[j] = al_o[rbase+j];
            pgo[j] = __fmul_rn(2.f, fabsf(ga_o[rbase+j]));
            float q = fabsf(om_o[rbase+j]); pwo[j] = __fmul_rn(q, q);
            bpv[j] = bp[rbase+j];
        }
    }

    float x_in[16], y_in[16], xr[16], yr[16], xo[16], yo[16];
    #pragma unroll
    for (int k = 0; k < 16; ++k) { x_in[k]=0.f; y_in[k]=0.f; xr[k]=0.f; yr[k]=0.f; xo[k]=0.f; yo[k]=0.f; }

    double lin = 0.0, lmse = 0.0;

    float inpv[16];
    {
        const float* p = inputs + (size_t)gb_i * (S_LEN * D_SZ) + dch;
        #pragma unroll
        for (int q = 0; q < 4; ++q) {
            float4 v = *(const float4*)(p + q*4);
            inpv[q*4]=v.x; inpv[q*4+1]=v.y; inpv[q*4+2]=v.z; inpv[q*4+3]=v.w;
        }
    }
    __syncthreads();   // staging complete before any use

    for (int t = 0; t < S_LEN; ++t) {
        float* xs = (t & 1) ? xs1 : xs0;

        if (t > 0) {
            float ls = 0.f;
            #pragma unroll
            for (int k = 0; k < 16; ++k) { float df = x_in[k]-inpv[k]; ls = fmaf(df, df, ls); }
            lin += (double)ls;
        }
        {
            float pav[16], pgv[16], pwv[16];
            #pragma unroll
            for (int q = 0; q < 4; ++q) {
                float4 a4 = *(const float4*)(pa + dch + q*4);
                float4 g4 = *(const float4*)(pg + dch + q*4);
                float4 w4 = *(const float4*)(pw + dch + q*4);
                pav[q*4]=a4.x; pav[q*4+1]=a4.y; pav[q*4+2]=a4.z; pav[q*4+3]=a4.w;
                pgv[q*4]=g4.x; pgv[q*4+1]=g4.y; pgv[q*4+2]=g4.z; pgv[q*4+3]=g4.w;
                pwv[q*4]=w4.x; pwv[q*4+1]=w4.y; pwv[q*4+2]=w4.z; pwv[q*4+3]=w4.w;
            }
            #pragma unroll
            for (int k = 0; k < 16; ++k)
                osc_upd(inpv[k], x_in[k], y_in[k], pav[k], pgv[k], pwv[k]);
        }
        #pragma unroll
        for (int k = 0; k < 16; ++k)
            xs[(dch + k) * 16 + irow] = x_in[k];
        __syncthreads();   // the ONLY barrier per step (double-buffered xs)

        {   // prefetch next input slice under the GEMM
            int tn = (t < S_LEN-1) ? t+1 : t;
            const float* p = inputs + (size_t)gb_i * (S_LEN*D_SZ) + (size_t)tn * D_SZ + dch;
            #pragma unroll
            for (int q = 0; q < 4; ++q) {
                float4 v = *(const float4*)(p + q*4);
                inpv[q*4]=v.x; inpv[q*4+1]=v.y; inpv[q*4+2]=v.z; inpv[q*4+3]=v.w;
            }
        }

        // GEMM1 tile: proj = x_in @ Wp^T  (per element: acc=0, ascending-d fma)
        ull acc[2][4];
        #pragma unroll
        for (int j = 0; j < 4; ++j) { acc[0][j] = 0ull; acc[1][j] = 0ull; }

        #pragma unroll 8
        for (int d = 0; d < 128; d += 2) {
            float4 xa = *(const float4*)(xs + d*16 + r0);
            float4 xb = *(const float4*)(xs + (d+1)*16 + r0);
            float4 wa = *(const float4*)(wt + d*128 + c0);
            float4 wb = *(const float4*)(wt + (d+1)*128 + c0);
            ull xa0 = pk2(xa.x, xa.y), xa1 = pk2(xa.z, xa.w);
            ull xb0 = pk2(xb.x, xb.y), xb1 = pk2(xb.z, xb.w);
            float wav[4] = {wa.x, wa.y, wa.z, wa.w};
            float wbv[4] = {wb.x, wb.y, wb.z, wb.w};
            #pragma unroll
            for (int j = 0; j < 4; ++j) {
                ull wda = pk2(wav[j], wav[j]);
                ull wdb = pk2(wbv[j], wbv[j]);
                acc[0][j] = fma2(xa0, wda, acc[0][j]);
                acc[1][j] = fma2(xa1, wda, acc[1][j]);
                acc[0][j] = fma2(xb0, wdb, acc[0][j]);
                acc[1][j] = fma2(xb1, wdb, acc[1][j]);
            }
        }

        float fv[4][4];
        #pragma unroll
        for (int rp = 0; rp < 2; ++rp)
            #pragma unroll
            for (int j = 0; j < 4; ++j) {
                float lo, hi; upk2(lo, hi, acc[rp][j]);
                fv[2*rp][j] = lo; fv[2*rp+1][j] = hi;
            }

        float ls2 = 0.f;
        #pragma unroll
        for (int i = 0; i < 4; ++i) {
            #pragma unroll
            for (int j = 0; j < 4; ++j) {
                int k = i*4 + j;
                float f = __fadd_rn(fv[i][j], bpv[j]);
                float xrn = osc_upd(f,   xr[k], yr[k], par[j], pgr[j], pwr[j]);
                float xon = osc_upd(xrn, xo[k], yo[k], pao[j], pgo[j], pwo[j]);
                float df = xon - xrn;
                ls2 = fmaf(df, df, ls2);
            }
        }
        lmse += (double)ls2;

        // hist_T[r][m]: r = cb*128+c0+j, m = t*256 + rb*16 + r0 + i (float4 over i)
        {
            int m = t * 256 + rb * 16 + r0;
            #pragma unroll
            for (int j = 0; j < 4; ++j) {
                size_t rrow = (size_t)(cb * 128 + c0 + j) * M_TOT;
                *(float4*)(g_hist + rrow + m) =
                    make_float4(xo[j], xo[4+j], xo[8+j], xo[12+j]);
            }
        }
    }

    __syncthreads();
    redd[tid] = lin; __syncthreads();
    for (int s = 64; s > 0; s >>= 1) { if (tid < s) redd[tid] += redd[tid+s]; __syncthreads(); }
    if (tid == 0 && cb == 0) g_pc_part[rb] = redd[0];
    __syncthreads();
    redd[tid] = lmse; __syncthreads();
    for (int s = 64; s > 0; s >>= 1) { if (tid < s) redd[tid] += redd[tid+s]; __syncthreads(); }
    if (tid == 0) g_mse_part[rb*16 + cb] = redd[0];
}

// ============ Phase B: preds = hist @ W_read^T + b_read ============
// CTA tile: 128 m-rows x 64 cols. Grid (1024, 2), 256 threads.
// cp.async double-buffered k-major staging from hist_T / WrT (no transposes).
#define WS_PITCH 68    // floats (4-divisible)
#define AS_PITCH 132   // floats (4-divisible)
#define WS_FLOATS (32 * WS_PITCH)
#define AS_FLOATS (32 * AS_PITCH)
__global__ void __launch_bounds__(256, 2) gemm2_kernel(
    const float* __restrict__ brd, float* __restrict__ out)
{
    __shared__ __align__(16) float ws[2][WS_FLOATS];
    __shared__ __align__(16) float as2[2][AS_FLOATS];

    const int tid = threadIdx.x;
    const int lane = tid & 31, warp = tid >> 5;
    const int rg = lane & 15, cg = lane >> 4;
    const int r0 = rg * 2;
    const int c0 = warp * 8 + cg * 4;
    const int C0 = blockIdx.y * 64;
    const size_t mBase = (size_t)blockIdx.x * 128;

    const uint32_t ws_b  = smem_u32(ws);
    const uint32_t as_b  = smem_u32(as2);

    ull acc[4][4];
    #pragma unroll
    for (int rp = 0; rp < 4; ++rp)
        #pragma unroll
        for (int j = 0; j < 4; ++j) acc[rp][j] = 0ull;

    // stage chunk 0 into buffer 0
    {
        uint32_t wsb = ws_b, asb = as_b;
        #pragma unroll
        for (int i0 = 0; i0 < 2; ++i0) {
            int i = tid + i0 * 256, k = i >> 4, g = i & 15;
            cp16(wsb + (uint32_t)(k * WS_PITCH + g*4) * 4,
                 g_WrT + (size_t)k * D_SZ + C0 + g*4);
        }
        #pragma unroll
        for (int i0 = 0; i0 < 4; ++i0) {
            int i = tid + i0 * 256, k = i >> 5, g = i & 31;
            cp16(asb + (uint32_t)(k * AS_PITCH + g*4) * 4,
                 g_hist + (size_t)k * M_TOT + mBase + g*4);
        }
        asm volatile("cp.async.commit_group;");
    }

    for (int c = 0; c < 64; ++c) {
        int buf = c & 1;
        if (c + 1 < 64) {   // prefetch next chunk into other buffer
            int kc = (c + 1) * 32, nb = buf ^ 1;
            uint32_t wsb = ws_b + (uint32_t)(nb * WS_FLOATS * 4);
            uint32_t asb = as_b + (uint32_t)(nb * AS_FLOATS * 4);
            #pragma unroll
            for (int i0 = 0; i0 < 2; ++i0) {
                int i = tid + i0 * 256, k = i >> 4, g = i & 15;
                cp16(wsb + (uint32_t)(k * WS_PITCH + g*4) * 4,
                     g_WrT + (size_t)(kc + k) * D_SZ + C0 + g*4);
            }
            #pragma unroll
            for (int i0 = 0; i0 < 4; ++i0) {
                int i = tid + i0 * 256, k = i >> 5, g = i & 31;
                cp16(asb + (uint32_t)(k * AS_PITCH + g*4) * 4,
                     g_hist + (size_t)(kc + k) * M_TOT + mBase + g*4);
            }
            asm volatile("cp.async.commit_group;");
            asm volatile("cp.async.wait_group 1;");
        } else {
            asm volatile("cp.async.wait_group 0;");
        }
        __syncthreads();

        const float* wsp = ws[buf];
        const float* asp = as2[buf];
        #pragma unroll 8
        for (int k = 0; k < 32; ++k) {
            float4 wv = *(const float4*)(wsp + k*WS_PITCH + c0);
            ull wd0 = pk2(wv.x, wv.x), wd1 = pk2(wv.y, wv.y);
            ull wd2 = pk2(wv.z, wv.z), wd3 = pk2(wv.w, wv.w);
            #pragma unroll
            for (int rp = 0; rp < 4; ++rp) {
                float2 xv = *(const float2*)(asp + k*AS_PITCH + rp*32 + r0);
                ull xp = pk2(xv.x, xv.y);
                acc[rp][0] = fma2(xp, wd0, acc[rp][0]);
                acc[rp][1] = fma2(xp, wd1, acc[rp][1]);
                acc[rp][2] = fma2(xp, wd2, acc[rp][2]);
                acc[rp][3] = fma2(xp, wd3, acc[rp][3]);
            }
        }
        __syncthreads();   // done reading buf before it's restaged
    }

    float bv[4];
    #pragma unroll
    for (int j = 0; j < 4; ++j) bv[j] = brd[C0 + c0 + j];

    #pragma unroll
    for (int rp = 0; rp < 4; ++rp) {
        float lo[4], hi[4];
        #pragma unroll
        for (int j = 0; j < 4; ++j) upk2(lo[j], hi[j], acc[rp][j]);
        #pragma unroll
        for (int h = 0; h < 2; ++h) {
            size_t m = mBase + rp*32 + r0 + h;
            int b = (int)(m & 255), t = (int)(m >> 8);
            float* o = out + (size_t)b * (S_LEN * D_SZ) + (size_t)t * D_SZ + C0 + c0;
            float* src = h ? hi : lo;
            *(float4*)(o) = make_float4(__fadd_rn(src[0], bv[0]), __fadd_rn(src[1], bv[1]),
                                        __fadd_rn(src[2], bv[2]), __fadd_rn(src[3], bv[3]));
        }
    }
}

// ============ Final loss reduce ============
__global__ void reduce_kernel(float* __restrict__ out, int out_size)
{
    if (threadIdx.x != 0 || blockIdx.x != 0) return;
    double a = 0.0, b = 0.0;
    for (int i = 0; i < 16; ++i)  a += g_pc_part[i];
    for (int i = 0; i < 256; ++i) b += g_mse_part[i];
    a /= (double)(B_SZ * D_SZ);
    b /= (double)(B_SZ * R_SZ);
    size_t base = (size_t)B_SZ * S_LEN * D_SZ;
    if ((size_t)out_size >= base + 2) {
        out[base]     = (float)a;
        out[base + 1] = (float)b;
    }
}

extern "C" void kernel_launch(void* const* d_in, const int* in_sizes, int n_in,
                              void* d_out, int out_size)
{
    const float* inputs = (const float*)d_in[0];
    const float* om_in  = (const float*)d_in[1];
    const float* ga_in  = (const float*)d_in[2];
    const float* al_in  = (const float*)d_in[3];
    const float* Wp     = (const float*)d_in[4];
    const float* bp     = (const float*)d_in[5];
    const float* om_r   = (const float*)d_in[6];
    const float* ga_r   = (const float*)d_in[7];
    const float* al_r   = (const float*)d_in[8];
    const float* om_o   = (const float*)d_in[9];
    const float* ga_o   = (const float*)d_in[10];
    const float* al_o   = (const float*)d_in[11];
    const float* Wr     = (const float*)d_in[12];
    const float* brd    = (const float*)d_in[13];
    float* out = (float*)d_out;

    cudaFuncSetAttribute(phaseA_kernel,
        cudaFuncAttributeMaxDynamicSharedMemorySize, 81920);

    dim3 tb(32, 8);
    dim3 tg(R_SZ / 32, D_SZ / 32);
    wrt_kernel<<<tg, tb>>>(Wr);

    dim3 gA(16, 16);
    phaseA_kernel<<<gA, 128, 81920>>>(inputs, om_in, ga_in, al_in, Wp, bp,
                                      om_r, ga_r, al_r, om_o, ga_o, al_o);
    dim3 gB(1024, 2);
    gemm2_kernel<<<gB, 256>>>(brd, out);
    reduce_kernel<<<1, 1>>>(out, out_size);
}

// round 17
// speedup vs baseline: 2.4636x; 1.0419x over previous
#include <cuda_runtime.h>
#include <cstdint>
#include <cstddef>

typedef unsigned long long ull;

#define S_LEN 512
#define B_SZ  256
#define D_SZ  128
#define R_SZ  2048
#define M_TOT (S_LEN * B_SZ)   // 131072

// hist transposed: g_hist[r][m], m = t*256 + b   (1 GiB)
__device__ float  g_hist[(size_t)R_SZ * M_TOT];
__device__ float  g_WrT[(size_t)R_SZ * D_SZ];    // WrT[k][c]
__device__ double g_pc_part[16];
__device__ double g_mse_part[256];

__device__ __forceinline__ ull pk2(float lo, float hi) {
    ull r; asm("mov.b64 %0, {%1,%2};" : "=l"(r) : "f"(lo), "f"(hi)); return r;
}
__device__ __forceinline__ void upk2(float& lo, float& hi, ull v) {
    asm("mov.b64 {%0,%1}, %2;" : "=f"(lo), "=f"(hi) : "l"(v));
}
__device__ __forceinline__ ull fma2(ull a, ull b, ull c) {
    ull d; asm("fma.rn.f32x2 %0, %1, %2, %3;" : "=l"(d) : "l"(a), "l"(b), "l"(c)); return d;
}
__device__ __forceinline__ float clip5(float v) { return fminf(fmaxf(v, -5.f), 5.f); }
__device__ __forceinline__ uint32_t smem_u32(const void* p) {
    uint32_t a;
    asm("{ .reg .u64 t; cvta.to.shared.u64 t, %1; cvt.u32.u64 %0, t; }" : "=r"(a) : "l"(p));
    return a;
}
__device__ __forceinline__ void cp16(uint32_t s, const void* g) {
    asm volatile("cp.async.cg.shared.global [%0], [%1], 16;" :: "r"(s), "l"(g));
}

// XLA:GPU-contracted oscillator step (matched recipe — DO NOT CHANGE)
__device__ __forceinline__ float osc_upd(float f, float& x, float& y,
                                         float a, float g2, float w2) {
    float gy = __fmul_rn(g2, y);
    float ac = fmaf(-w2, x, fmaf(a, f, -gy));
    float xn = clip5(fmaf(0.5f, y, x));
    float yn = clip5(fmaf(0.5f, ac, y));
    x = xn; y = yn;
    return xn;
}

// ============ W_read transpose: WrT[k][c] = Wr[c][k] ============
__global__ void wrt_kernel(const float* __restrict__ Wr)
{
    __shared__ float tile[32][33];
    int kBase = blockIdx.x * 32, cBase = blockIdx.y * 32;
    int tx = threadIdx.x, ty = threadIdx.y;   // 32 x 8
    #pragma unroll
    for (int q = 0; q < 32; q += 8)
        tile[ty + q][tx] = Wr[(size_t)(cBase + ty + q) * R_SZ + kBase + tx];
    __syncthreads();
    #pragma unroll
    for (int q = 0; q < 32; q += 8)
        g_WrT[(size_t)(kBase + ty + q) * D_SZ + cBase + tx] = tile[tx][ty + q];
}

// ============ Phase A: persistent recurrence ============
// Grid (16 col-blocks, 16 row-blocks of 16 rows), 128 threads, 2 CTAs/SM.
__global__ void __launch_bounds__(128, 2) phaseA_kernel(
    const float* __restrict__ inputs,
    const float* __restrict__ om_in, const float* __restrict__ ga_in, const float* __restrict__ al_in,
    const float* __restrict__ Wp,    const float* __restrict__ bp,
    const float* __restrict__ om_r,  const float* __restrict__ ga_r,  const float* __restrict__ al_r,
    const float* __restrict__ om_o,  const float* __restrict__ ga_o,  const float* __restrict__ al_o)
{
    const int cb  = blockIdx.x;   // 0..15 reservoir col block
    const int rb  = blockIdx.y;   // 0..15 batch row block (16 rows)
    const int tid = threadIdx.x;

    extern __shared__ float smem[];
    float* wt  = smem;                    // [128 d][128 c]
    float* xs0 = smem + 128 * 128;        // [128 d][16 rows]
    float* xs1 = xs0 + 128 * 16;

    __shared__ float  pa[128], pg[128], pw[128];
    __shared__ double redd[128];

    for (int i = tid; i < 4096; i += 128) {
        int c = i >> 5, d0 = (i & 31) << 2;
        float4 v = *(const float4*)(Wp + ((size_t)(cb * 128 + c)) * D_SZ + d0);
        wt[(d0+0)*128 + c] = v.x; wt[(d0+1)*128 + c] = v.y;
        wt[(d0+2)*128 + c] = v.z; wt[(d0+3)*128 + c] = v.w;
    }
    {
        pa[tid] = al_in[tid];
        pg[tid] = __fmul_rn(2.f, fabsf(ga_in[tid]));
        float o = fabsf(om_in[tid]); pw[tid] = __fmul_rn(o, o);
    }

    const int irow = tid & 15;            // 0..15
    const int dch  = (tid >> 4) << 4;     // chunk*16
    const int gb_i = rb * 16 + irow;

    const int lane = tid & 31, warp = tid >> 5;
    const int r0 = (lane & 3) << 2;                 // 0,4,8,12
    const int c0 = warp * 32 + ((lane >> 2) << 2);  // 8 col-groups x 4

    float par[4], pgr[4], pwr[4], pao[4], pgo[4], pwo[4], bpv[4];
    {
        int rbase = cb * 128 + c0;
        #pragma unroll
        for (int j = 0; j < 4; ++j) {
            par[j] = al_r[rbase+j];
            pgr[j] = __fmul_rn(2.f, fabsf(ga_r[rbase+j]));
            float o = fabsf(om_r[rbase+j]); pwr[j] = __fmul_rn(o, o);
            pao[j] = al_o[rbase+j];
            pgo[j] = __fmul_rn(2.f, fabsf(ga_o[rbase+j]));
            float q = fabsf(om_o[rbase+j]); pwo[j] = __fmul_rn(q, q);
            bpv[j] = bp[rbase+j];
        }
    }

    float x_in[16], y_in[16], xr[16], yr[16], xo[16], yo[16];
    #pragma unroll
    for (int k = 0; k < 16; ++k) { x_in[k]=0.f; y_in[k]=0.f; xr[k]=0.f; yr[k]=0.f; xo[k]=0.f; yo[k]=0.f; }

    double lin = 0.0, lmse = 0.0;

    float inpv[16];
    {
        const float* p = inputs + (size_t)gb_i * (S_LEN * D_SZ) + dch;
        #pragma unroll
        for (int q = 0; q < 4; ++q) {
            float4 v = *(const float4*)(p + q*4);
            inpv[q*4]=v.x; inpv[q*4+1]=v.y; inpv[q*4+2]=v.z; inpv[q*4+3]=v.w;
        }
    }
    __syncthreads();   // staging complete before any use

    for (int t = 0; t < S_LEN; ++t) {
        float* xs = (t & 1) ? xs1 : xs0;

        if (t > 0) {
            float ls = 0.f;
            #pragma unroll
            for (int k = 0; k < 16; ++k) { float df = x_in[k]-inpv[k]; ls = fmaf(df, df, ls); }
            lin += (double)ls;
        }
        {
            float pav[16], pgv[16], pwv[16];
            #pragma unroll
            for (int q = 0; q < 4; ++q) {
                float4 a4 = *(const float4*)(pa + dch + q*4);
                float4 g4 = *(const float4*)(pg + dch + q*4);
                float4 w4 = *(const float4*)(pw + dch + q*4);
                pav[q*4]=a4.x; pav[q*4+1]=a4.y; pav[q*4+2]=a4.z; pav[q*4+3]=a4.w;
                pgv[q*4]=g4.x; pgv[q*4+1]=g4.y; pgv[q*4+2]=g4.z; pgv[q*4+3]=g4.w;
                pwv[q*4]=w4.x; pwv[q*4+1]=w4.y; pwv[q*4+2]=w4.z; pwv[q*4+3]=w4.w;
            }
            #pragma unroll
            for (int k = 0; k < 16; ++k)
                osc_upd(inpv[k], x_in[k], y_in[k], pav[k], pgv[k], pwv[k]);
        }
        #pragma unroll
        for (int k = 0; k < 16; ++k)
            xs[(dch + k) * 16 + irow] = x_in[k];

        {   // prefetch next input slice BEFORE barrier: latency overlaps barrier+GEMM
            int tn = (t < S_LEN-1) ? t+1 : t;
            const float* p = inputs + (size_t)gb_i * (S_LEN*D_SZ) + (size_t)tn * D_SZ + dch;
            #pragma unroll
            for (int q = 0; q < 4; ++q) {
                float4 v = *(const float4*)(p + q*4);
                inpv[q*4]=v.x; inpv[q*4+1]=v.y; inpv[q*4+2]=v.z; inpv[q*4+3]=v.w;
            }
        }
        __syncthreads();   // the ONLY barrier per step (double-buffered xs)

        // GEMM1 tile: proj = x_in @ Wp^T  (per element: acc=0, ascending-d fma)
        ull acc[2][4];
        #pragma unroll
        for (int j = 0; j < 4; ++j) { acc[0][j] = 0ull; acc[1][j] = 0ull; }

        #pragma unroll 8
        for (int d = 0; d < 128; d += 2) {
            float4 xa = *(const float4*)(xs + d*16 + r0);
            float4 xb = *(const float4*)(xs + (d+1)*16 + r0);
            float4 wa = *(const float4*)(wt + d*128 + c0);
            float4 wb = *(const float4*)(wt + (d+1)*128 + c0);
            ull xa0 = pk2(xa.x, xa.y), xa1 = pk2(xa.z, xa.w);
            ull xb0 = pk2(xb.x, xb.y), xb1 = pk2(xb.z, xb.w);
            float wav[4] = {wa.x, wa.y, wa.z, wa.w};
            float wbv[4] = {wb.x, wb.y, wb.z, wb.w};
            #pragma unroll
            for (int j = 0; j < 4; ++j) {
                ull wda = pk2(wav[j], wav[j]);
                ull wdb = pk2(wbv[j], wbv[j]);
                acc[0][j] = fma2(xa0, wda, acc[0][j]);
                acc[1][j] = fma2(xa1, wda, acc[1][j]);
                acc[0][j] = fma2(xb0, wdb, acc[0][j]);
                acc[1][j] = fma2(xb1, wdb, acc[1][j]);
            }
        }

        float fv[4][4];
        #pragma unroll
        for (int rp = 0; rp < 2; ++rp)
            #pragma unroll
            for (int j = 0; j < 4; ++j) {
                float lo, hi; upk2(lo, hi, acc[rp][j]);
                fv[2*rp][j] = lo; fv[2*rp+1][j] = hi;
            }

        float ls2 = 0.f;
        #pragma unroll
        for (int i = 0; i < 4; ++i) {
            #pragma unroll
            for (int j = 0; j < 4; ++j) {
                int k = i*4 + j;
                float f = __fadd_rn(fv[i][j], bpv[j]);
                float xrn = osc_upd(f,   xr[k], yr[k], par[j], pgr[j], pwr[j]);
                float xon = osc_upd(xrn, xo[k], yo[k], pao[j], pgo[j], pwo[j]);
                float df = xon - xrn;
                ls2 = fmaf(df, df, ls2);
            }
        }
        lmse += (double)ls2;

        // hist_T[r][m]: r = cb*128+c0+j, m = t*256 + rb*16 + r0 + i (float4 over i)
        {
            int m = t * 256 + rb * 16 + r0;
            #pragma unroll
            for (int j = 0; j < 4; ++j) {
                size_t rrow = (size_t)(cb * 128 + c0 + j) * M_TOT;
                *(float4*)(g_hist + rrow + m) =
                    make_float4(xo[j], xo[4+j], xo[8+j], xo[12+j]);
            }
        }
    }

    __syncthreads();
    redd[tid] = lin; __syncthreads();
    for (int s = 64; s > 0; s >>= 1) { if (tid < s) redd[tid] += redd[tid+s]; __syncthreads(); }
    if (tid == 0 && cb == 0) g_pc_part[rb] = redd[0];
    __syncthreads();
    redd[tid] = lmse; __syncthreads();
    for (int s = 64; s > 0; s >>= 1) { if (tid < s) redd[tid] += redd[tid+s]; __syncthreads(); }
    if (tid == 0) g_mse_part[rb*16 + cb] = redd[0];
}

// ============ Phase B: preds = hist @ W_read^T + b_read ============
// CTA tile: 128 m-rows x 128 cols. Grid (1024), 256 threads, thread 8r x 8c.
// cp.async double-buffered k-major staging from hist_T / WrT.
#define GP 132   // smem pitch in floats for both 32x128 chunks
#define BUF_FLOATS (32 * GP)
__global__ void __launch_bounds__(256, 1) gemm2_kernel(
    const float* __restrict__ brd, float* __restrict__ out)
{
    __shared__ __align__(16) float ws[2][BUF_FLOATS];    // ws[buf][k*GP + c]
    __shared__ __align__(16) float as2[2][BUF_FLOATS];   // as2[buf][k*GP + m']

    const int tid = threadIdx.x;
    const int lane = tid & 31, warp = tid >> 5;
    const int rg = lane & 15;                 // 16 row groups of 8
    const int r0 = rg * 8;
    const int c0 = warp * 16 + ((lane >> 4) << 3);   // 16 col groups of 8
    const size_t mBase = (size_t)blockIdx.x * 128;

    const uint32_t ws_b = smem_u32(ws);
    const uint32_t as_b = smem_u32(as2);

    ull acc[4][8];   // rp row-pair (rows r0+2rp, r0+2rp+1), j col
    #pragma unroll
    for (int rp = 0; rp < 4; ++rp)
        #pragma unroll
        for (int j = 0; j < 8; ++j) acc[rp][j] = 0ull;

    // stage chunk 0 into buffer 0: 4 cp16 each for W and hist
    {
        int k = tid >> 5, g4 = (tid & 31) << 2;   // 32 threads per k-row
        #pragma unroll
        for (int q = 0; q < 4; ++q) {
            int kk = k + q * 8;
            cp16(ws_b + (uint32_t)(kk * GP + g4) * 4, g_WrT + (size_t)kk * D_SZ + g4);
            cp16(as_b + (uint32_t)(kk * GP + g4) * 4, g_hist + (size_t)kk * M_TOT + mBase + g4);
        }
        asm volatile("cp.async.commit_group;");
    }

    for (int c = 0; c < 64; ++c) {
        int buf = c & 1;
        if (c + 1 < 64) {
            int kc = (c + 1) * 32, nb = buf ^ 1;
            uint32_t wsb = ws_b + (uint32_t)(nb * BUF_FLOATS * 4);
            uint32_t asb = as_b + (uint32_t)(nb * BUF_FLOATS * 4);
            int k = tid >> 5, g4 = (tid & 31) << 2;
            #pragma unroll
            for (int q = 0; q < 4; ++q) {
                int kk = k + q * 8;
                cp16(wsb + (uint32_t)(kk * GP + g4) * 4,
                     g_WrT + (size_t)(kc + kk) * D_SZ + g4);
                cp16(asb + (uint32_t)(kk * GP + g4) * 4,
                     g_hist + (size_t)(kc + kk) * M_TOT + mBase + g4);
            }
            asm volatile("cp.async.commit_group;");
            asm volatile("cp.async.wait_group 1;");
        } else {
            asm volatile("cp.async.wait_group 0;");
        }
        __syncthreads();

        const float* wsp = ws[buf];
        const float* asp = as2[buf];
        #pragma unroll 4
        for (int k = 0; k < 32; ++k) {
            float4 wv0 = *(const float4*)(wsp + k*GP + c0);
            float4 wv1 = *(const float4*)(wsp + k*GP + c0 + 4);
            float4 xv0 = *(const float4*)(asp + k*GP + r0);       // rows r0..r0+3
            float4 xv1 = *(const float4*)(asp + k*GP + r0 + 4);   // rows r0+4..r0+7
            ull xp0 = pk2(xv0.x, xv0.y), xp1 = pk2(xv0.z, xv0.w);
            ull xp2 = pk2(xv1.x, xv1.y), xp3 = pk2(xv1.z, xv1.w);
            float wv[8] = {wv0.x, wv0.y, wv0.z, wv0.w, wv1.x, wv1.y, wv1.z, wv1.w};
            #pragma unroll
            for (int j = 0; j < 8; ++j) {
                ull wd = pk2(wv[j], wv[j]);
                acc[0][j] = fma2(xp0, wd, acc[0][j]);
                acc[1][j] = fma2(xp1, wd, acc[1][j]);
                acc[2][j] = fma2(xp2, wd, acc[2][j]);
                acc[3][j] = fma2(xp3, wd, acc[3][j]);
            }
        }
        __syncthreads();   // done reading buf before it's restaged
    }

    float bv[8];
    #pragma unroll
    for (int j = 0; j < 8; ++j) bv[j] = brd[c0 + j];

    #pragma unroll
    for (int rp = 0; rp < 4; ++rp) {
        float lo[8], hi[8];
        #pragma unroll
        for (int j = 0; j < 8; ++j) upk2(lo[j], hi[j], acc[rp][j]);
        #pragma unroll
        for (int h = 0; h < 2; ++h) {
            size_t m = mBase + r0 + 2*rp + h;
            int b = (int)(m & 255), t = (int)(m >> 8);
            float* o = out + (size_t)b * (S_LEN * D_SZ) + (size_t)t * D_SZ + c0;
            float* src = h ? hi : lo;
            *(float4*)(o)     = make_float4(__fadd_rn(src[0], bv[0]), __fadd_rn(src[1], bv[1]),
                                            __fadd_rn(src[2], bv[2]), __fadd_rn(src[3], bv[3]));
            *(float4*)(o + 4) = make_float4(__fadd_rn(src[4], bv[4]), __fadd_rn(src[5], bv[5]),
                                            __fadd_rn(src[6], bv[6]), __fadd_rn(src[7], bv[7]));
        }
    }
}

// ============ Final loss reduce ============
__global__ void reduce_kernel(float* __restrict__ out, int out_size)
{
    if (threadIdx.x != 0 || blockIdx.x != 0) return;
    double a = 0.0, b = 0.0;
    for (int i = 0; i < 16; ++i)  a += g_pc_part[i];
    for (int i = 0; i < 256; ++i) b += g_mse_part[i];
    a /= (double)(B_SZ * D_SZ);
    b /= (double)(B_SZ * R_SZ);
    size_t base = (size_t)B_SZ * S_LEN * D_SZ;
    if ((size_t)out_size >= base + 2) {
        out[base]     = (float)a;
        out[base + 1] = (float)b;
    }
}

extern "C" void kernel_launch(void* const* d_in, const int* in_sizes, int n_in,
                              void* d_out, int out_size)
{
    const float* inputs = (const float*)d_in[0];
    const float* om_in  = (const float*)d_in[1];
    const float* ga_in  = (const float*)d_in[2];
    const float* al_in  = (const float*)d_in[3];
    const float* Wp     = (const float*)d_in[4];
    const float* bp     = (const float*)d_in[5];
    const float* om_r   = (const float*)d_in[6];
    const float* ga_r   = (const float*)d_in[7];
    const float* al_r   = (const float*)d_in[8];
    const float* om_o   = (const float*)d_in[9];
    const float* ga_o   = (const float*)d_in[10];
    const float* al_o   = (const float*)d_in[11];
    const float* Wr     = (const float*)d_in[12];
    const float* brd    = (const float*)d_in[13];
    float* out = (float*)d_out;

    cudaFuncSetAttribute(phaseA_kernel,
        cudaFuncAttributeMaxDynamicSharedMemorySize, 81920);

    dim3 tb(32, 8);
    dim3 tg(R_SZ / 32, D_SZ / 32);
    wrt_kernel<<<tg, tb>>>(Wr);

    dim3 gA(16, 16);
    phaseA_kernel<<<gA, 128, 81920>>>(inputs, om_in, ga_in, al_in, Wp, bp,
                                      om_r, ga_r, al_r, om_o, ga_o, al_o);
    gemm2_kernel<<<1024, 256>>>(brd, out);
    reduce_kernel<<<1, 1>>>(out, out_size);
}